// round 9
// baseline (speedup 1.0000x reference)
#include <cuda_runtime.h>
#include <stdint.h>

// PureAEVComputer radial AEV, two-kernel: per-batch species sort (4 blocks),
// then lean compute kernel (128 thr, 2 rows/block, 2 warps/row).
// Approx-intrinsic math (ex2.approx / rsqrt.approx).

#define NB 4
#define NN 1024
#define PAD 1152                      // 1024 + 4*31 = 1148 -> 1152
#define OUTW 1008
#define RC2 27.04f
#define RCF 5.2f
#define PI_OVER_RC 0.6041524334f
#define LLCF 23.083120654223414f      // eta * log2(e), eta=16
#define KPF  12.407177351645084f      // 2 * LLC * 0.26875
#define SA 1.70625f                   // anchor A = shell 3
#define SB 3.85625f                   // anchor B = shell 11
#define T1C   0.31486064f
#define T4C   0.009828185f
#define T9C   3.0413467e-5f
#define T16C  9.3302500e-9f
#define IT16C 1.0717934e8f

__device__ float4 g_sorted[NB * PAD];
__device__ int    g_ps[NB * 5];

__device__ __forceinline__ float ex2a(float x) {
    float r; asm("ex2.approx.f32 %0, %1;" : "=f"(r) : "f"(x)); return r;
}
__device__ __forceinline__ float rsqa(float x) {
    float r; asm("rsqrt.approx.f32 %0, %1;" : "=f"(r) : "f"(x)); return r;
}

// ---------------------------------------------------------------------------
// Kernel A: per-batch counting sort by species into g_sorted (+ g_ps).
// One block per batch, 256 threads.
// ---------------------------------------------------------------------------
__global__ void __launch_bounds__(256)
sort_kernel(const int* __restrict__ spw, const float* __restrict__ coords) {
    __shared__ unsigned char sspb[NN];
    __shared__ int wcnt[8][4];
    __shared__ int woff[8][4];
    __shared__ int sbase[5];
    __shared__ int sbad;

    const int b    = blockIdx.x;
    const int tid  = threadIdx.x;
    const int w    = tid >> 5;
    const int lane = tid & 31;
    const unsigned full = 0xffffffffu;

    if (tid == 0) sbad = 0;
    // sentinel fill (far away => contributes exactly 0)
    for (int t = tid; t < PAD; t += 256)
        g_sorted[b * PAD + t] = make_float4(1e9f, 1e9f, 1e9f, 0.f);
    __syncthreads();

    // detect int64 vs int32 from first 512 elements (safe either way)
    int bad = 0;
    for (int q = tid; q < 512; q += 256) {
        int lo = spw[2 * q], hi = spw[2 * q + 1];
        if (hi != 0 || ((unsigned)lo) > 3u) bad = 1;
    }
    if (bad) atomicOr(&sbad, 1);
    __syncthreads();
    const int is64 = !sbad;

    for (int e = tid; e < NN; e += 256) {
        int sp = is64 ? spw[2 * (b * NN + e)] : spw[b * NN + e];
        sspb[e] = (unsigned char)sp;
    }
    __syncthreads();

    // per-warp histogram (warp w owns [w*128, w*128+128))
    {
        int c0 = 0, c1 = 0, c2 = 0, c3 = 0;
        for (int it = 0; it < 4; ++it) {
            int sp = sspb[w * 128 + it * 32 + lane];
            c0 += __popc(__ballot_sync(full, sp == 0));
            c1 += __popc(__ballot_sync(full, sp == 1));
            c2 += __popc(__ballot_sync(full, sp == 2));
            c3 += __popc(__ballot_sync(full, sp == 3));
        }
        if (lane == 0) {
            wcnt[w][0] = c0; wcnt[w][1] = c1; wcnt[w][2] = c2; wcnt[w][3] = c3;
        }
    }
    __syncthreads();

    if (tid == 0) {
        int basep = 0;
        for (int s = 0; s < 4; ++s) {
            sbase[s] = basep;
            int tot = 0;
            for (int ww = 0; ww < 8; ++ww) { woff[ww][s] = basep + tot; tot += wcnt[ww][s]; }
            basep += (tot + 31) & ~31;
        }
        sbase[4] = basep;
    }
    __syncthreads();

    if (tid < 5) g_ps[b * 5 + tid] = sbase[tid];

    // scatter coords into species-sorted global buffer
    {
        const unsigned lt = (1u << lane) - 1u;
        int u0 = 0, u1 = 0, u2 = 0, u3 = 0;
        for (int it = 0; it < 4; ++it) {
            int e  = w * 128 + it * 32 + lane;
            int sp = sspb[e];
            unsigned m0 = __ballot_sync(full, sp == 0);
            unsigned m1 = __ballot_sync(full, sp == 1);
            unsigned m2 = __ballot_sync(full, sp == 2);
            unsigned m3 = __ballot_sync(full, sp == 3);
            int pos;
            if (sp == 0)      pos = woff[w][0] + u0 + __popc(m0 & lt);
            else if (sp == 1) pos = woff[w][1] + u1 + __popc(m1 & lt);
            else if (sp == 2) pos = woff[w][2] + u2 + __popc(m2 & lt);
            else              pos = woff[w][3] + u3 + __popc(m3 & lt);
            const float* cp = coords + (size_t)(b * NN + e) * 3;
            g_sorted[b * PAD + pos] = make_float4(cp[0], cp[1], cp[2], 0.f);
            u0 += __popc(m0); u1 += __popc(m1); u2 += __popc(m2); u3 += __popc(m3);
        }
    }
}

// ---------------------------------------------------------------------------
// Kernel B: compute. 128 threads = 4 warps = 2 rows x 2 species-pair warps.
// ---------------------------------------------------------------------------
__global__ void __launch_bounds__(128, 11)
aev_main(const float* __restrict__ coords, float* __restrict__ out) {
    __shared__ float4 sco[PAD];
    __shared__ int    sbase[5];

    const int tid  = threadIdx.x;
    const int w    = tid >> 5;
    const int lane = tid & 31;
    const int b      = blockIdx.x >> 9;        // 512 blocks per batch
    const int rowblk = blockIdx.x & 511;       // 2 rows per block
    const unsigned full = 0xffffffffu;

    for (int t = tid; t < PAD; t += 128)
        sco[t] = g_sorted[b * PAD + t];
    if (tid < 5) sbase[tid] = g_ps[b * 5 + tid];
    __syncthreads();

    // zero output tails for both rows (floats [64,1008) = f4 [16,252))
    {
        const float4 z4 = make_float4(0.f, 0.f, 0.f, 0.f);
        for (int r = 0; r < 2; ++r) {
            float4* o4 = (float4*)(out + (size_t)(b * NN + rowblk * 2 + r) * OUTW);
            for (int c = 16 + tid; c < 252; c += 128) o4[c] = z4;
        }
    }

    const int i  = rowblk * 2 + (w >> 1);
    const int s0 = (w & 1) * 2;

    const float* cc = coords + (size_t)(b * NN + i) * 3;
    const float xi = cc[0], yi = cc[1], zi = cc[2];
    float* orow = out + (size_t)(b * NN + i) * OUTW;

    const int b0 = lane & 1, b1 = (lane >> 1) & 1, b2 = (lane >> 2) & 1,
              b3 = (lane >> 3) & 1;

#pragma unroll
    for (int ss = 0; ss < 2; ++ss) {
        const int s = s0 + ss;
        float acc[16];
#pragma unroll
        for (int k = 0; k < 16; ++k) acc[k] = 0.f;

        const int en = sbase[s + 1];
        for (int t = sbase[s] + lane; t < en; t += 32) {
            float4 cj = sco[t];
            float dx = xi - cj.x, dy = yi - cj.y, dz = zi - cj.z;
            float d2 = fmaf(dx, dx, fmaf(dy, dy, dz * dz));
            bool ok = (d2 > 0.f) && (d2 <= RC2);
            float d  = d2 * rsqa(d2);              // NaN at d2==0
            float dm = fminf(d, RCF);              // NaN/far -> 5.2
            float fcv = fmaf(0.5f, __cosf(dm * PI_OVER_RC), 0.5f);
            float fc = ok ? fcv : 0.f;             // exact masking

            float fa = dm - SA;
            float ga = ex2a((-LLCF * fa) * fa);
            float fb = dm - SB;
            float gb = ex2a((-LLCF * fb) * fb);
            float pa = ex2a(fmaf(KPF, dm, -KPF * SA));
            float qa = ex2a(fmaf(-KPF, dm, KPF * SA));
            float pb = pa * T16C;
            float qb = qa * IT16C;
            float hA = fc * ga;
            float hB = fc * gb;

            acc[3]  += hA;
            acc[11] += hB;
            float h;
            h = hA * pa; acc[4]  = fmaf(h, T1C,  acc[4]);
            h *= pa;     acc[5]  = fmaf(h, T4C,  acc[5]);
            h *= pa;     acc[6]  = fmaf(h, T9C,  acc[6]);
            h *= pa;     acc[7]  = fmaf(h, T16C, acc[7]);
            h = hA * qa; acc[2]  = fmaf(h, T1C,  acc[2]);
            h *= qa;     acc[1]  = fmaf(h, T4C,  acc[1]);
            h *= qa;     acc[0]  = fmaf(h, T9C,  acc[0]);
            h = hB * pb; acc[12] = fmaf(h, T1C,  acc[12]);
            h *= pb;     acc[13] = fmaf(h, T4C,  acc[13]);
            h *= pb;     acc[14] = fmaf(h, T9C,  acc[14]);
            h *= pb;     acc[15] = fmaf(h, T16C, acc[15]);
            h = hB * qb; acc[10] = fmaf(h, T1C,  acc[10]);
            h *= qb;     acc[9]  = fmaf(h, T4C,  acc[9]);
            h *= qb;     acc[8]  = fmaf(h, T9C,  acc[8]);
        }

        // ---- shell-distributing butterfly reduction ----
        float v[8];
#pragma unroll
        for (int j = 0; j < 8; ++j) {
            float snd = b0 ? acc[2 * j] : acc[2 * j + 1];
            float rcv = __shfl_xor_sync(full, snd, 1);
            v[j] = (b0 ? acc[2 * j + 1] : acc[2 * j]) + rcv;
        }
        float vv[4];
#pragma unroll
        for (int j = 0; j < 4; ++j) {
            float snd = b1 ? v[2 * j] : v[2 * j + 1];
            float rcv = __shfl_xor_sync(full, snd, 2);
            vv[j] = (b1 ? v[2 * j + 1] : v[2 * j]) + rcv;
        }
        float x0, x1;
        {
            float snd = b2 ? vv[0] : vv[1];
            float rcv = __shfl_xor_sync(full, snd, 4);
            x0 = (b2 ? vv[1] : vv[0]) + rcv;
            snd = b2 ? vv[2] : vv[3];
            rcv = __shfl_xor_sync(full, snd, 4);
            x1 = (b2 ? vv[3] : vv[2]) + rcv;
        }
        float y;
        {
            float snd = b3 ? x0 : x1;
            float rcv = __shfl_xor_sync(full, snd, 8);
            y = (b3 ? x1 : x0) + rcv;
        }
        y += __shfl_xor_sync(full, y, 16);

        if (lane < 16) orow[s * 16 + lane] = y;
    }
}

extern "C" void kernel_launch(void* const* d_in, const int* in_sizes, int n_in,
                              void* d_out, int out_size) {
    (void)in_sizes; (void)n_in; (void)out_size;
    const int*   spec   = (const int*)d_in[0];
    const float* coords = (const float*)d_in[1];
    float*       out    = (float*)d_out;

    sort_kernel<<<NB, 256>>>(spec, coords);
    aev_main<<<NB * (NN / 2), 128>>>(coords, out);
}

// round 12
// speedup vs baseline: 1.0072x; 1.0072x over previous
#include <cuda_runtime.h>
#include <stdint.h>

// PureAEVComputer radial AEV, fused kernel. Anchor-chain Gaussians,
// polynomial cutoff (no COS), unroll-2 ILP mainloop. Segments padded to 64.

#define NB 4
#define NN 1024
#define PAD 1280                      // 1024 + 4*63 = 1276 -> 1280
#define OUTW 1008
#define RC2 27.04f
#define INV_RC2 0.03698224852071006f
#define RCF 5.2f
#define LLCF 23.083120654223414f      // eta * log2(e), eta=16
#define KPF  12.407177351645084f      // 2 * LLC * 0.26875
#define SA 1.70625f
#define SB 3.85625f
#define T1C   0.31486064f
#define T4C   0.009828185f
#define T9C   3.0413467e-5f
#define T16C  9.3302500e-9f
#define IT16C 1.0717934e8f
// fc(u) = 0.5 + 0.5*cos(pi*sqrt(u)), u = d^2/Rc^2, Taylor deg-7 (abs err <5e-6)
#define C0 1.0f
#define C1 (-2.4674011002723397f)
#define C2 (2.0293560632083984f)
#define C3 (-0.6676312134387305f)
#define C4 (0.1176653137496378f)
#define C5 (-0.0129034455736919f)
#define C6 (0.0009647871347870f)
#define C7 (-0.0000523185f)

__device__ __forceinline__ float ex2a(float x) {
    float r; asm("ex2.approx.f32 %0, %1;" : "=f"(r) : "f"(x)); return r;
}
__device__ __forceinline__ float rsqa(float x) {
    float r; asm("rsqrt.approx.f32 %0, %1;" : "=f"(r) : "f"(x)); return r;
}

__global__ void __launch_bounds__(256, 5)
aev_fused(const int* __restrict__ spw, const float* __restrict__ coords,
          float* __restrict__ out) {
    __shared__ float4        sco[PAD];
    __shared__ unsigned char sspb[NN];
    __shared__ int           wcnt[8][4];
    __shared__ int           woff[8][4];
    __shared__ int           sbase[5];
    __shared__ int           sbad;

    const int tid  = threadIdx.x;
    const int w    = tid >> 5;
    const int lane = tid & 31;
    const int b      = blockIdx.x >> 8;        // 256 blocks per batch
    const int rowblk = blockIdx.x & 255;       // 4 rows per block
    const unsigned full = 0xffffffffu;

    if (tid == 0) sbad = 0;
    for (int t = tid; t < PAD; t += 256)
        sco[t] = make_float4(1e9f, 1e9f, 1e9f, 0.f);
    __syncthreads();

    // ---- detect int64 vs int32 ----
    int bad = 0;
    for (int q = tid; q < 512; q += 256) {
        int lo = spw[2 * q], hi = spw[2 * q + 1];
        if (hi != 0 || ((unsigned)lo) > 3u) bad = 1;
    }
    if (bad) atomicOr(&sbad, 1);
    __syncthreads();
    const int is64 = !sbad;

    for (int e = tid; e < NN; e += 256) {
        int sp = is64 ? spw[2 * (b * NN + e)] : spw[b * NN + e];
        sspb[e] = (unsigned char)sp;
    }
    __syncthreads();

    // ---- per-warp histogram ----
    {
        int c0 = 0, c1 = 0, c2 = 0, c3 = 0;
        for (int it = 0; it < 4; ++it) {
            int sp = sspb[w * 128 + it * 32 + lane];
            c0 += __popc(__ballot_sync(full, sp == 0));
            c1 += __popc(__ballot_sync(full, sp == 1));
            c2 += __popc(__ballot_sync(full, sp == 2));
            c3 += __popc(__ballot_sync(full, sp == 3));
        }
        if (lane == 0) {
            wcnt[w][0] = c0; wcnt[w][1] = c1; wcnt[w][2] = c2; wcnt[w][3] = c3;
        }
    }
    __syncthreads();

    if (tid == 0) {
        int basep = 0;
        for (int s = 0; s < 4; ++s) {
            sbase[s] = basep;
            int tot = 0;
            for (int ww = 0; ww < 8; ++ww) { woff[ww][s] = basep + tot; tot += wcnt[ww][s]; }
            basep += (tot + 63) & ~63;          // pad segments to 64
        }
        sbase[4] = basep;
    }
    __syncthreads();

    // ---- scatter coords ----
    {
        const unsigned lt = (1u << lane) - 1u;
        int u0 = 0, u1 = 0, u2 = 0, u3 = 0;
        for (int it = 0; it < 4; ++it) {
            int e  = w * 128 + it * 32 + lane;
            int sp = sspb[e];
            unsigned m0 = __ballot_sync(full, sp == 0);
            unsigned m1 = __ballot_sync(full, sp == 1);
            unsigned m2 = __ballot_sync(full, sp == 2);
            unsigned m3 = __ballot_sync(full, sp == 3);
            int pos;
            if (sp == 0)      pos = woff[w][0] + u0 + __popc(m0 & lt);
            else if (sp == 1) pos = woff[w][1] + u1 + __popc(m1 & lt);
            else if (sp == 2) pos = woff[w][2] + u2 + __popc(m2 & lt);
            else              pos = woff[w][3] + u3 + __popc(m3 & lt);
            const float* cp = coords + (size_t)(b * NN + e) * 3;
            sco[pos] = make_float4(cp[0], cp[1], cp[2], 0.f);
            u0 += __popc(m0); u1 += __popc(m1); u2 += __popc(m2); u3 += __popc(m3);
        }
    }
    __syncthreads();

    // ---- zero output tails for the 4 rows ----
    {
        const float4 z4 = make_float4(0.f, 0.f, 0.f, 0.f);
        for (int r = 0; r < 4; ++r) {
            float4* o4 = (float4*)(out + (size_t)(b * NN + rowblk * 4 + r) * OUTW);
            for (int c = 16 + tid; c < 252; c += 256) o4[c] = z4;
        }
    }

    // =================== main compute ===================
    const int i  = rowblk * 4 + (w >> 1);
    const int s0 = (w & 1) * 2;

    const float* cc = coords + (size_t)(b * NN + i) * 3;
    const float xi = cc[0], yi = cc[1], zi = cc[2];
    float* orow = out + (size_t)(b * NN + i) * OUTW;

    const int b0 = lane & 1, b1 = (lane >> 1) & 1, b2 = (lane >> 2) & 1,
              b3 = (lane >> 3) & 1;

#pragma unroll
    for (int ss = 0; ss < 2; ++ss) {
        const int s = s0 + ss;
        float acc[16];
#pragma unroll
        for (int k = 0; k < 16; ++k) acc[k] = 0.f;

        const int st = sbase[s], en = sbase[s + 1];
        for (int t = st + lane; t < en; t += 64) {
            // two independent elements in flight
            float4 cjA = sco[t];
            float4 cjB = sco[t + 32];

            float dxA = xi - cjA.x, dyA = yi - cjA.y, dzA = zi - cjA.z;
            float dxB = xi - cjB.x, dyB = yi - cjB.y, dzB = zi - cjB.z;
            float d2A = fmaf(dxA, dxA, fmaf(dyA, dyA, dzA * dzA));
            float d2B = fmaf(dxB, dxB, fmaf(dyB, dyB, dzB * dzB));
            bool okA = (d2A > 0.f) && (d2A <= RC2);
            bool okB = (d2B > 0.f) && (d2B <= RC2);

            float uA = d2A * INV_RC2, uB = d2B * INV_RC2;
            float pcA = fmaf(C7, uA, C6), pcB = fmaf(C7, uB, C6);
            pcA = fmaf(pcA, uA, C5);  pcB = fmaf(pcB, uB, C5);
            pcA = fmaf(pcA, uA, C4);  pcB = fmaf(pcB, uB, C4);
            pcA = fmaf(pcA, uA, C3);  pcB = fmaf(pcB, uB, C3);
            pcA = fmaf(pcA, uA, C2);  pcB = fmaf(pcB, uB, C2);
            pcA = fmaf(pcA, uA, C1);  pcB = fmaf(pcB, uB, C1);
            pcA = fmaf(pcA, uA, C0);  pcB = fmaf(pcB, uB, C0);
            float fcA = okA ? pcA : 0.f;
            float fcB = okB ? pcB : 0.f;

            float dA = d2A * rsqa(d2A);          // NaN at 0, masked
            float dB = d2B * rsqa(d2B);
            float dmA = fminf(dA, RCF);
            float dmB = fminf(dB, RCF);

            float faA = dmA - SA, faB = dmB - SA;
            float gaA = ex2a((-LLCF * faA) * faA);
            float gaB = ex2a((-LLCF * faB) * faB);
            float fbA = dmA - SB, fbB = dmB - SB;
            float gbA = ex2a((-LLCF * fbA) * fbA);
            float gbB = ex2a((-LLCF * fbB) * fbB);
            float paA = ex2a(fmaf(KPF, dmA, -KPF * SA));
            float paB = ex2a(fmaf(KPF, dmB, -KPF * SA));
            float qaA = ex2a(fmaf(-KPF, dmA, KPF * SA));
            float qaB = ex2a(fmaf(-KPF, dmB, KPF * SA));
            float pbA = paA * T16C, pbB = paB * T16C;
            float qbA = qaA * IT16C, qbB = qaB * IT16C;
            float hAA = fcA * gaA, hAB = fcB * gaB;
            float hBA = fcA * gbA, hBB = fcB * gbB;

            acc[3]  += hAA + hAB;
            acc[11] += hBA + hBB;
            float h0, h1;
            h0 = hAA * paA; h1 = hAB * paB;
            acc[4]  = fmaf(h0, T1C,  fmaf(h1, T1C,  acc[4]));
            h0 *= paA; h1 *= paB;
            acc[5]  = fmaf(h0, T4C,  fmaf(h1, T4C,  acc[5]));
            h0 *= paA; h1 *= paB;
            acc[6]  = fmaf(h0, T9C,  fmaf(h1, T9C,  acc[6]));
            h0 *= paA; h1 *= paB;
            acc[7]  = fmaf(h0, T16C, fmaf(h1, T16C, acc[7]));
            h0 = hAA * qaA; h1 = hAB * qaB;
            acc[2]  = fmaf(h0, T1C,  fmaf(h1, T1C,  acc[2]));
            h0 *= qaA; h1 *= qaB;
            acc[1]  = fmaf(h0, T4C,  fmaf(h1, T4C,  acc[1]));
            h0 *= qaA; h1 *= qaB;
            acc[0]  = fmaf(h0, T9C,  fmaf(h1, T9C,  acc[0]));
            h0 = hBA * pbA; h1 = hBB * pbB;
            acc[12] = fmaf(h0, T1C,  fmaf(h1, T1C,  acc[12]));
            h0 *= pbA; h1 *= pbB;
            acc[13] = fmaf(h0, T4C,  fmaf(h1, T4C,  acc[13]));
            h0 *= pbA; h1 *= pbB;
            acc[14] = fmaf(h0, T9C,  fmaf(h1, T9C,  acc[14]));
            h0 *= pbA; h1 *= pbB;
            acc[15] = fmaf(h0, T16C, fmaf(h1, T16C, acc[15]));
            h0 = hBA * qbA; h1 = hBB * qbB;
            acc[10] = fmaf(h0, T1C,  fmaf(h1, T1C,  acc[10]));
            h0 *= qbA; h1 *= qbB;
            acc[9]  = fmaf(h0, T4C,  fmaf(h1, T4C,  acc[9]));
            h0 *= qbA; h1 *= qbB;
            acc[8]  = fmaf(h0, T9C,  fmaf(h1, T9C,  acc[8]));
        }

        // ---- shell-distributing butterfly reduction ----
        float v[8];
#pragma unroll
        for (int j = 0; j < 8; ++j) {
            float snd = b0 ? acc[2 * j] : acc[2 * j + 1];
            float rcv = __shfl_xor_sync(full, snd, 1);
            v[j] = (b0 ? acc[2 * j + 1] : acc[2 * j]) + rcv;
        }
        float vv[4];
#pragma unroll
        for (int j = 0; j < 4; ++j) {
            float snd = b1 ? v[2 * j] : v[2 * j + 1];
            float rcv = __shfl_xor_sync(full, snd, 2);
            vv[j] = (b1 ? v[2 * j + 1] : v[2 * j]) + rcv;
        }
        float x0, x1;
        {
            float snd = b2 ? vv[0] : vv[1];
            float rcv = __shfl_xor_sync(full, snd, 4);
            x0 = (b2 ? vv[1] : vv[0]) + rcv;
            snd = b2 ? vv[2] : vv[3];
            rcv = __shfl_xor_sync(full, snd, 4);
            x1 = (b2 ? vv[3] : vv[2]) + rcv;
        }
        float y;
        {
            float snd = b3 ? x0 : x1;
            float rcv = __shfl_xor_sync(full, snd, 8);
            y = (b3 ? x1 : x0) + rcv;
        }
        y += __shfl_xor_sync(full, y, 16);

        if (lane < 16) orow[s * 16 + lane] = y;
    }
}

extern "C" void kernel_launch(void* const* d_in, const int* in_sizes, int n_in,
                              void* d_out, int out_size) {
    (void)in_sizes; (void)n_in; (void)out_size;
    const int*   spec   = (const int*)d_in[0];
    const float* coords = (const float*)d_in[1];
    float*       out    = (float*)d_out;

    aev_fused<<<NB * (NN / 4), 256>>>(spec, coords, out);
}

// round 13
// speedup vs baseline: 1.0926x; 1.0847x over previous
#include <cuda_runtime.h>
#include <stdint.h>

// PureAEVComputer radial AEV. Persistent-style wave-exact grid:
// 592 blocks (4/SM x 148), each block owns ONE batch (batch = blockIdx&3),
// strided 2-row groups, 1 warp = (row, species). Anchor-chain Gaussians.

#define NB 4
#define NN 1024
#define PAD 1152                      // 1024 + 4*31 -> 1152
#define OUTW 1008
#define NGRID 592                     // 4 blocks/SM * 148 SMs
#define NGROUP 2048                   // 2-row groups total (4 batches x 512)
#define RC2 27.04f
#define RCF 5.2f
#define PI_OVER_RC 0.6041524334f
#define LLCF 23.083120654223414f      // eta * log2(e), eta=16
#define KPF  12.407177351645084f      // 2 * LLC * 0.26875
#define SA 1.70625f
#define SB 3.85625f
#define T1C   0.31486064f
#define T4C   0.009828185f
#define T9C   3.0413467e-5f
#define T16C  9.3302500e-9f
#define IT16C 1.0717934e8f

__device__ __forceinline__ float ex2a(float x) {
    float r; asm("ex2.approx.f32 %0, %1;" : "=f"(r) : "f"(x)); return r;
}
__device__ __forceinline__ float rsqa(float x) {
    float r; asm("rsqrt.approx.f32 %0, %1;" : "=f"(r) : "f"(x)); return r;
}

__global__ void __launch_bounds__(256, 4)
aev_persist(const int* __restrict__ spw, const float* __restrict__ coords,
            float* __restrict__ out) {
    __shared__ float4        sco[PAD];
    __shared__ unsigned char sspb[NN];
    __shared__ int           wcnt[8][4];
    __shared__ int           woff[8][4];
    __shared__ int           sbase[5];
    __shared__ int           sbad;

    const int tid  = threadIdx.x;
    const int w    = tid >> 5;
    const int lane = tid & 31;
    const int b    = blockIdx.x & 3;           // block's (only) batch
    const unsigned full = 0xffffffffu;

    // ======================= prologue: sort batch b =======================
    if (tid == 0) sbad = 0;
    for (int t = tid; t < PAD; t += 256)
        sco[t] = make_float4(1e9f, 1e9f, 1e9f, 0.f);
    __syncthreads();

    int bad = 0;
    for (int q = tid; q < 512; q += 256) {
        int lo = spw[2 * q], hi = spw[2 * q + 1];
        if (hi != 0 || ((unsigned)lo) > 3u) bad = 1;
    }
    if (bad) atomicOr(&sbad, 1);
    __syncthreads();
    const int is64 = !sbad;

    for (int e = tid; e < NN; e += 256) {
        int sp = is64 ? spw[2 * (b * NN + e)] : spw[b * NN + e];
        sspb[e] = (unsigned char)sp;
    }
    __syncthreads();

    {
        int c0 = 0, c1 = 0, c2 = 0, c3 = 0;
        for (int it = 0; it < 4; ++it) {
            int sp = sspb[w * 128 + it * 32 + lane];
            c0 += __popc(__ballot_sync(full, sp == 0));
            c1 += __popc(__ballot_sync(full, sp == 1));
            c2 += __popc(__ballot_sync(full, sp == 2));
            c3 += __popc(__ballot_sync(full, sp == 3));
        }
        if (lane == 0) {
            wcnt[w][0] = c0; wcnt[w][1] = c1; wcnt[w][2] = c2; wcnt[w][3] = c3;
        }
    }
    __syncthreads();

    if (tid == 0) {
        int basep = 0;
        for (int s = 0; s < 4; ++s) {
            sbase[s] = basep;
            int tot = 0;
            for (int ww = 0; ww < 8; ++ww) { woff[ww][s] = basep + tot; tot += wcnt[ww][s]; }
            basep += (tot + 31) & ~31;
        }
        sbase[4] = basep;
    }
    __syncthreads();

    {
        const unsigned lt = (1u << lane) - 1u;
        int u0 = 0, u1 = 0, u2 = 0, u3 = 0;
        for (int it = 0; it < 4; ++it) {
            int e  = w * 128 + it * 32 + lane;
            int sp = sspb[e];
            unsigned m0 = __ballot_sync(full, sp == 0);
            unsigned m1 = __ballot_sync(full, sp == 1);
            unsigned m2 = __ballot_sync(full, sp == 2);
            unsigned m3 = __ballot_sync(full, sp == 3);
            int pos;
            if (sp == 0)      pos = woff[w][0] + u0 + __popc(m0 & lt);
            else if (sp == 1) pos = woff[w][1] + u1 + __popc(m1 & lt);
            else if (sp == 2) pos = woff[w][2] + u2 + __popc(m2 & lt);
            else              pos = woff[w][3] + u3 + __popc(m3 & lt);
            const float* cp = coords + (size_t)(b * NN + e) * 3;
            sco[pos] = make_float4(cp[0], cp[1], cp[2], 0.f);
            u0 += __popc(m0); u1 += __popc(m1); u2 += __popc(m2); u3 += __popc(m3);
        }
    }
    __syncthreads();

    // warp-local constants
    const int s  = w & 3;                      // this warp's species
    const int ro = w >> 2;                     // row offset within group (0/1)
    const int st = sbase[s], en = sbase[s + 1];
    const int b0 = lane & 1, b1 = (lane >> 1) & 1, b2 = (lane >> 2) & 1,
              b3 = (lane >> 3) & 1;

    // ================= group loop (no syncs; warps drift) =================
    for (int g = blockIdx.x; g < NGROUP; g += NGRID) {
        const int i = ((g >> 2) << 1) + ro;    // row within batch
        float* orow = out + (size_t)(b * NN + i) * OUTW;

        // species-3 warps zero their row's tail [64,1008) = f4 [16,252)
        if (s == 3) {
            float4* o4 = (float4*)orow;
            const float4 z4 = make_float4(0.f, 0.f, 0.f, 0.f);
            for (int c = 16 + lane; c < 252; c += 32) o4[c] = z4;
        }

        const float* cc = coords + (size_t)(b * NN + i) * 3;
        const float xi = cc[0], yi = cc[1], zi = cc[2];

        float acc[16];
#pragma unroll
        for (int k = 0; k < 16; ++k) acc[k] = 0.f;

        for (int t = st + lane; t < en; t += 32) {
            float4 cj = sco[t];
            float dx = xi - cj.x, dy = yi - cj.y, dz = zi - cj.z;
            float d2 = fmaf(dx, dx, fmaf(dy, dy, dz * dz));
            bool ok = (d2 > 0.f) && (d2 <= RC2);
            float d  = d2 * rsqa(d2);            // NaN at d2==0, masked
            float dm = fminf(d, RCF);            // NaN/far -> 5.2
            float fcv = fmaf(0.5f, __cosf(dm * PI_OVER_RC), 0.5f);
            float fc = ok ? fcv : 0.f;           // exact masking

            float fa = dm - SA;
            float ga = ex2a((-LLCF * fa) * fa);
            float fb = dm - SB;
            float gb = ex2a((-LLCF * fb) * fb);
            float pa = ex2a(fmaf(KPF, dm, -KPF * SA));
            float qa = ex2a(fmaf(-KPF, dm, KPF * SA));
            float pb = pa * T16C;
            float qb = qa * IT16C;
            float hA = fc * ga;
            float hB = fc * gb;

            acc[3]  += hA;
            acc[11] += hB;
            float h;
            h = hA * pa; acc[4]  = fmaf(h, T1C,  acc[4]);
            h *= pa;     acc[5]  = fmaf(h, T4C,  acc[5]);
            h *= pa;     acc[6]  = fmaf(h, T9C,  acc[6]);
            h *= pa;     acc[7]  = fmaf(h, T16C, acc[7]);
            h = hA * qa; acc[2]  = fmaf(h, T1C,  acc[2]);
            h *= qa;     acc[1]  = fmaf(h, T4C,  acc[1]);
            h *= qa;     acc[0]  = fmaf(h, T9C,  acc[0]);
            h = hB * pb; acc[12] = fmaf(h, T1C,  acc[12]);
            h *= pb;     acc[13] = fmaf(h, T4C,  acc[13]);
            h *= pb;     acc[14] = fmaf(h, T9C,  acc[14]);
            h *= pb;     acc[15] = fmaf(h, T16C, acc[15]);
            h = hB * qb; acc[10] = fmaf(h, T1C,  acc[10]);
            h *= qb;     acc[9]  = fmaf(h, T4C,  acc[9]);
            h *= qb;     acc[8]  = fmaf(h, T9C,  acc[8]);
        }

        // ---- shell-distributing butterfly reduction ----
        float v[8];
#pragma unroll
        for (int j = 0; j < 8; ++j) {
            float snd = b0 ? acc[2 * j] : acc[2 * j + 1];
            float rcv = __shfl_xor_sync(full, snd, 1);
            v[j] = (b0 ? acc[2 * j + 1] : acc[2 * j]) + rcv;
        }
        float vv[4];
#pragma unroll
        for (int j = 0; j < 4; ++j) {
            float snd = b1 ? v[2 * j] : v[2 * j + 1];
            float rcv = __shfl_xor_sync(full, snd, 2);
            vv[j] = (b1 ? v[2 * j + 1] : v[2 * j]) + rcv;
        }
        float x0, x1;
        {
            float snd = b2 ? vv[0] : vv[1];
            float rcv = __shfl_xor_sync(full, snd, 4);
            x0 = (b2 ? vv[1] : vv[0]) + rcv;
            snd = b2 ? vv[2] : vv[3];
            rcv = __shfl_xor_sync(full, snd, 4);
            x1 = (b2 ? vv[3] : vv[2]) + rcv;
        }
        float y;
        {
            float snd = b3 ? x0 : x1;
            float rcv = __shfl_xor_sync(full, snd, 8);
            y = (b3 ? x1 : x0) + rcv;
        }
        y += __shfl_xor_sync(full, y, 16);

        if (lane < 16) orow[s * 16 + lane] = y;
    }
}

extern "C" void kernel_launch(void* const* d_in, const int* in_sizes, int n_in,
                              void* d_out, int out_size) {
    (void)in_sizes; (void)n_in; (void)out_size;
    const int*   spec   = (const int*)d_in[0];
    const float* coords = (const float*)d_in[1];
    float*       out    = (float*)d_out;

    aev_persist<<<NGRID, 256>>>(spec, coords, out);
}

// round 14
// speedup vs baseline: 1.1836x; 1.0833x over previous
#include <cuda_runtime.h>
#include <stdint.h>

// PureAEVComputer radial AEV, fused kernel (R6 structure), anchor-chain
// Gaussians with PACKED f32x2 accumulation (Blackwell mul/fma.rn.f32x2).

#define NB 4
#define NN 1024
#define PAD 1280
#define OUTW 1008
#define RC2 27.04f
#define RCF 5.2f
#define PI_OVER_RC 0.6041524334f
#define LLCF 23.083120654223414f      // eta * log2(e), eta=16
#define KPF  12.407177351645084f      // 2 * LLC * 0.26875
#define SA 1.70625f
#define SB 3.85625f
#define T1C   0.31486064f
#define T4C   0.009828185f
#define T9C   3.0413467e-5f
#define T16C  9.3302500e-9f
#define IT16C 1.0717934e8f

typedef unsigned long long u64;

__device__ __forceinline__ float ex2a(float x) {
    float r; asm("ex2.approx.f32 %0, %1;" : "=f"(r) : "f"(x)); return r;
}
__device__ __forceinline__ float rsqa(float x) {
    float r; asm("rsqrt.approx.f32 %0, %1;" : "=f"(r) : "f"(x)); return r;
}
__device__ __forceinline__ u64 pk2(float lo, float hi) {
    u64 r; asm("mov.b64 %0, {%1, %2};" : "=l"(r) : "f"(lo), "f"(hi)); return r;
}
__device__ __forceinline__ void upk2(float& lo, float& hi, u64 v) {
    asm("mov.b64 {%0, %1}, %2;" : "=f"(lo), "=f"(hi) : "l"(v));
}
__device__ __forceinline__ u64 mul2(u64 a, u64 b) {
    u64 r; asm("mul.rn.f32x2 %0, %1, %2;" : "=l"(r) : "l"(a), "l"(b)); return r;
}
__device__ __forceinline__ u64 add2(u64 a, u64 b) {
    u64 r; asm("add.rn.f32x2 %0, %1, %2;" : "=l"(r) : "l"(a), "l"(b)); return r;
}
__device__ __forceinline__ u64 fma2(u64 a, u64 b, u64 c) {
    u64 r; asm("fma.rn.f32x2 %0, %1, %2, %3;" : "=l"(r) : "l"(a), "l"(b), "l"(c)); return r;
}

__global__ void __launch_bounds__(256, 5)
aev_fused(const int* __restrict__ spw, const float* __restrict__ coords,
          float* __restrict__ out) {
    __shared__ float4        sco[PAD];
    __shared__ unsigned char sspb[NN];
    __shared__ int           wcnt[8][4];
    __shared__ int           woff[8][4];
    __shared__ int           sbase[5];
    __shared__ int           sbad;

    const int tid  = threadIdx.x;
    const int w    = tid >> 5;
    const int lane = tid & 31;
    const int b      = blockIdx.x >> 8;        // 256 blocks per batch
    const int rowblk = blockIdx.x & 255;       // 4 rows per block
    const unsigned full = 0xffffffffu;

    if (tid == 0) sbad = 0;
    for (int t = tid; t < PAD; t += 256)
        sco[t] = make_float4(1e9f, 1e9f, 1e9f, 0.f);
    __syncthreads();

    // ---- detect int64 vs int32 ----
    int bad = 0;
    for (int q = tid; q < 512; q += 256) {
        int lo = spw[2 * q], hi = spw[2 * q + 1];
        if (hi != 0 || ((unsigned)lo) > 3u) bad = 1;
    }
    if (bad) atomicOr(&sbad, 1);
    __syncthreads();
    const int is64 = !sbad;

    for (int e = tid; e < NN; e += 256) {
        int sp = is64 ? spw[2 * (b * NN + e)] : spw[b * NN + e];
        sspb[e] = (unsigned char)sp;
    }
    __syncthreads();

    // ---- per-warp histogram ----
    {
        int c0 = 0, c1 = 0, c2 = 0, c3 = 0;
        for (int it = 0; it < 4; ++it) {
            int sp = sspb[w * 128 + it * 32 + lane];
            c0 += __popc(__ballot_sync(full, sp == 0));
            c1 += __popc(__ballot_sync(full, sp == 1));
            c2 += __popc(__ballot_sync(full, sp == 2));
            c3 += __popc(__ballot_sync(full, sp == 3));
        }
        if (lane == 0) {
            wcnt[w][0] = c0; wcnt[w][1] = c1; wcnt[w][2] = c2; wcnt[w][3] = c3;
        }
    }
    __syncthreads();

    if (tid == 0) {
        int basep = 0;
        for (int s = 0; s < 4; ++s) {
            sbase[s] = basep;
            int tot = 0;
            for (int ww = 0; ww < 8; ++ww) { woff[ww][s] = basep + tot; tot += wcnt[ww][s]; }
            basep += (tot + 31) & ~31;
        }
        sbase[4] = basep;
    }
    __syncthreads();

    // ---- scatter coords ----
    {
        const unsigned lt = (1u << lane) - 1u;
        int u0 = 0, u1 = 0, u2 = 0, u3 = 0;
        for (int it = 0; it < 4; ++it) {
            int e  = w * 128 + it * 32 + lane;
            int sp = sspb[e];
            unsigned m0 = __ballot_sync(full, sp == 0);
            unsigned m1 = __ballot_sync(full, sp == 1);
            unsigned m2 = __ballot_sync(full, sp == 2);
            unsigned m3 = __ballot_sync(full, sp == 3);
            int pos;
            if (sp == 0)      pos = woff[w][0] + u0 + __popc(m0 & lt);
            else if (sp == 1) pos = woff[w][1] + u1 + __popc(m1 & lt);
            else if (sp == 2) pos = woff[w][2] + u2 + __popc(m2 & lt);
            else              pos = woff[w][3] + u3 + __popc(m3 & lt);
            const float* cp = coords + (size_t)(b * NN + e) * 3;
            sco[pos] = make_float4(cp[0], cp[1], cp[2], 0.f);
            u0 += __popc(m0); u1 += __popc(m1); u2 += __popc(m2); u3 += __popc(m3);
        }
    }
    __syncthreads();

    // ---- zero output tails for the 4 rows ----
    {
        const float4 z4 = make_float4(0.f, 0.f, 0.f, 0.f);
        for (int r = 0; r < 4; ++r) {
            float4* o4 = (float4*)(out + (size_t)(b * NN + rowblk * 4 + r) * OUTW);
            for (int c = 16 + tid; c < 252; c += 256) o4[c] = z4;
        }
    }

    // =================== main compute ===================
    const int i  = rowblk * 4 + (w >> 1);
    const int s0 = (w & 1) * 2;

    const float* cc = coords + (size_t)(b * NN + i) * 3;
    const float xi = cc[0], yi = cc[1], zi = cc[2];
    float* orow = out + (size_t)(b * NN + i) * OUTW;

    const int b0 = lane & 1, b1 = (lane >> 1) & 1, b2 = (lane >> 2) & 1,
              b3 = (lane >> 3) & 1;

    const u64 cT1  = pk2(T1C,  T1C);
    const u64 cT4  = pk2(T4C,  T4C);
    const u64 cT9  = pk2(T9C,  T9C);
    const u64 cT16 = pk2(T16C, T16C);

#pragma unroll
    for (int ss = 0; ss < 2; ++ss) {
        const int s = s0 + ss;
        // packed accumulators: [0..3]=up m=1..4 -> shells (4,12)(5,13)(6,14)(7,15)
        //                      [4..6]=down m=1..3 -> shells (2,10)(1,9)(0,8)
        //                      [7]=anchors (3,11)
        u64 acc2[8];
#pragma unroll
        for (int k = 0; k < 8; ++k) acc2[k] = 0ull;

        const int st = sbase[s], en = sbase[s + 1];
        for (int t = st + lane; t < en; t += 32) {
            float4 cj = sco[t];
            float dx = xi - cj.x, dy = yi - cj.y, dz = zi - cj.z;
            float d2 = fmaf(dx, dx, fmaf(dy, dy, dz * dz));
            bool ok = (d2 > 0.f) && (d2 <= RC2);
            float d  = d2 * rsqa(d2);              // NaN at 0, masked
            float dm = fminf(d, RCF);              // NaN/far -> 5.2
            float fcv = fmaf(0.5f, __cosf(dm * PI_OVER_RC), 0.5f);
            float fc = ok ? fcv : 0.f;             // exact masking

            float fa = dm - SA;
            float ga = ex2a((-LLCF * fa) * fa);
            float fb = dm - SB;
            float gb = ex2a((-LLCF * fb) * fb);
            float pa = ex2a(fmaf(KPF, dm, -KPF * SA));
            float qa = ex2a(fmaf(-KPF, dm, KPF * SA));
            float pb = pa * T16C;
            float qb = qa * IT16C;

            u64 hAB = mul2(pk2(ga, gb), pk2(fc, fc));   // (hA, hB)
            u64 up  = pk2(pa, pb);
            u64 dn  = pk2(qa, qb);

            acc2[7] = add2(acc2[7], hAB);
            u64 h = mul2(hAB, up);
            acc2[0] = fma2(h, cT1,  acc2[0]); h = mul2(h, up);
            acc2[1] = fma2(h, cT4,  acc2[1]); h = mul2(h, up);
            acc2[2] = fma2(h, cT9,  acc2[2]); h = mul2(h, up);
            acc2[3] = fma2(h, cT16, acc2[3]);
            h = mul2(hAB, dn);
            acc2[4] = fma2(h, cT1,  acc2[4]); h = mul2(h, dn);
            acc2[5] = fma2(h, cT4,  acc2[5]); h = mul2(h, dn);
            acc2[6] = fma2(h, cT9,  acc2[6]);
        }

        // unpack to scalar shell accumulators
        float acc[16];
        upk2(acc[3],  acc[11], acc2[7]);
        upk2(acc[4],  acc[12], acc2[0]);
        upk2(acc[5],  acc[13], acc2[1]);
        upk2(acc[6],  acc[14], acc2[2]);
        upk2(acc[7],  acc[15], acc2[3]);
        upk2(acc[2],  acc[10], acc2[4]);
        upk2(acc[1],  acc[9],  acc2[5]);
        upk2(acc[0],  acc[8],  acc2[6]);

        // ---- shell-distributing butterfly reduction ----
        float v[8];
#pragma unroll
        for (int j = 0; j < 8; ++j) {
            float snd = b0 ? acc[2 * j] : acc[2 * j + 1];
            float rcv = __shfl_xor_sync(full, snd, 1);
            v[j] = (b0 ? acc[2 * j + 1] : acc[2 * j]) + rcv;
        }
        float vv[4];
#pragma unroll
        for (int j = 0; j < 4; ++j) {
            float snd = b1 ? v[2 * j] : v[2 * j + 1];
            float rcv = __shfl_xor_sync(full, snd, 2);
            vv[j] = (b1 ? v[2 * j + 1] : v[2 * j]) + rcv;
        }
        float x0, x1;
        {
            float snd = b2 ? vv[0] : vv[1];
            float rcv = __shfl_xor_sync(full, snd, 4);
            x0 = (b2 ? vv[1] : vv[0]) + rcv;
            snd = b2 ? vv[2] : vv[3];
            rcv = __shfl_xor_sync(full, snd, 4);
            x1 = (b2 ? vv[3] : vv[2]) + rcv;
        }
        float y;
        {
            float snd = b3 ? x0 : x1;
            float rcv = __shfl_xor_sync(full, snd, 8);
            y = (b3 ? x1 : x0) + rcv;
        }
        y += __shfl_xor_sync(full, y, 16);

        if (lane < 16) orow[s * 16 + lane] = y;
    }
}

extern "C" void kernel_launch(void* const* d_in, const int* in_sizes, int n_in,
                              void* d_out, int out_size) {
    (void)in_sizes; (void)n_in; (void)out_size;
    const int*   spec   = (const int*)d_in[0];
    const float* coords = (const float*)d_in[1];
    float*       out    = (float*)d_out;

    aev_fused<<<NB * (NN / 4), 256>>>(spec, coords, out);
}